// round 1
// baseline (speedup 1.0000x reference)
#include <cuda_runtime.h>
#include <math.h>
#include <stddef.h>

// ---------------------------------------------------------------------------
// MultiHeadPooledAttention — fp32 baseline, pooling folded into projections.
// ---------------------------------------------------------------------------

namespace {
constexpr int B_  = 2;
constexpr int L_  = 6273;   // 1 + 8*28*28
constexpr int DM_ = 512;
constexpr int NH_ = 8;
constexpr int HD_ = 512;
constexpr int DH_ = NH_ * HD_;   // 4096
constexpr int LP_ = 1569;        // 1 + 8*14*14
constexpr int NB_ = 1568;
constexpr float SCALE_ = 0.04419417382415922f;  // 512^-0.5

// scratch layout (floats)
constexpr size_t SZ_WPT  = (size_t)3 * 4 * 512 * 512;     // transposed pool weights
constexpr size_t SZ_WEFF = (size_t)3 * 4096 * 2048;       // fused proj+pool weights
constexpr size_t SZ_WXE  = (size_t)512 * 2048;            // wpx as (512,2048)
constexpr size_t SZ_BP   = (size_t)3 * 4096;               // pooled biases
constexpr size_t SZ_XG   = (size_t)B_ * NB_ * 2048;        // gathered x windows
constexpr size_t SZ_P    = (size_t)B_ * NH_ * LP_ * HD_;   // PQ/PK/PV/K2
constexpr size_t SZ_PX   = (size_t)B_ * LP_ * DM_;
constexpr size_t SZ_EMB  = (size_t)NB_ * HD_;
constexpr size_t SZ_LG   = (size_t)B_ * NH_ * LP_ * LP_;
constexpr size_t SZ_ST   = (size_t)B_ * LP_ * DH_;

constexpr size_t OFF_WPT  = 0;
constexpr size_t OFF_WEFF = OFF_WPT + SZ_WPT;
constexpr size_t OFF_WXE  = OFF_WEFF + SZ_WEFF;
constexpr size_t OFF_BP   = OFF_WXE + SZ_WXE;
constexpr size_t OFF_XG   = OFF_BP + SZ_BP;
constexpr size_t OFF_PQ   = OFF_XG + SZ_XG;
constexpr size_t OFF_PK   = OFF_PQ + SZ_P;
constexpr size_t OFF_PV   = OFF_PK + SZ_P;
constexpr size_t OFF_K2   = OFF_PV + SZ_P;
constexpr size_t OFF_PX   = OFF_K2 + SZ_P;
constexpr size_t OFF_EMB  = OFF_PX + SZ_PX;
constexpr size_t OFF_LG   = OFF_EMB + SZ_EMB;
constexpr size_t OFF_ST   = OFF_LG + SZ_LG;
constexpr size_t SZ_TOTAL = OFF_ST + SZ_ST;
}  // namespace

__device__ float g_scratch[SZ_TOTAL];

// ---------------------------------------------------------------------------
// Generic 128x128x16 tiled SGEMM, 256 threads, 8x8 register tiles.
// P provides: constexpr bool BT (true: B is (N,K) row-major, C = A*B^T;
//             false: B is (K,N) row-major, C = A*B), Aptr/Bptr/store, dims.
// ---------------------------------------------------------------------------
template <typename P>
__global__ __launch_bounds__(256) void gemm_tile(P p) {
  __shared__ float As[16][132];
  __shared__ float Bs[16][132];

  const int z = blockIdx.z;
  const float* A = p.Aptr(z);
  const float* B = p.Bptr(z);
  const int M = p.M, N = p.N, K = p.K;
  const int lda = p.lda, ldb = p.ldb;

  const int m0 = blockIdx.y * 128;
  const int n0 = blockIdx.x * 128;
  const int tid = threadIdx.x;
  const int tx = tid & 15;    // col group
  const int ty = tid >> 4;    // row group

  const int lk = tid & 15;    // k index for tile loads
  const int lr = tid >> 4;    // base row for tile loads

  float acc[8][8];
#pragma unroll
  for (int i = 0; i < 8; i++)
#pragma unroll
    for (int j = 0; j < 8; j++) acc[i][j] = 0.f;

  for (int k0 = 0; k0 < K; k0 += 16) {
    // load A tile: As[k][m] = A[m0+m][k0+k]
#pragma unroll
    for (int i = 0; i < 8; i++) {
      int m = lr + i * 16;
      int gm = m0 + m, gk = k0 + lk;
      float v = (gm < M && gk < K) ? A[(size_t)gm * lda + gk] : 0.f;
      As[lk][m] = v;
    }
    if (P::BT) {
      // B is (N,K): Bs[k][n] = B[n0+n][k0+k]
#pragma unroll
      for (int i = 0; i < 8; i++) {
        int n = lr + i * 16;
        int gn = n0 + n, gk = k0 + lk;
        float v = (gn < N && gk < K) ? B[(size_t)gn * ldb + gk] : 0.f;
        Bs[lk][n] = v;
      }
    } else {
      // B is (K,N): Bs[k][n] = B[k0+k][n0+n]
      int n = tid & 127;
      int kb = tid >> 7;
#pragma unroll
      for (int i = 0; i < 8; i++) {
        int k = kb + i * 2;
        int gk = k0 + k, gn = n0 + n;
        float v = (gk < K && gn < N) ? B[(size_t)gk * ldb + gn] : 0.f;
        Bs[k][n] = v;
      }
    }
    __syncthreads();

#pragma unroll
    for (int kk = 0; kk < 16; kk++) {
      float4 a0 = *reinterpret_cast<const float4*>(&As[kk][ty * 8]);
      float4 a1 = *reinterpret_cast<const float4*>(&As[kk][ty * 8 + 4]);
      float4 b0 = *reinterpret_cast<const float4*>(&Bs[kk][tx * 8]);
      float4 b1 = *reinterpret_cast<const float4*>(&Bs[kk][tx * 8 + 4]);
      float a[8] = {a0.x, a0.y, a0.z, a0.w, a1.x, a1.y, a1.z, a1.w};
      float b[8] = {b0.x, b0.y, b0.z, b0.w, b1.x, b1.y, b1.z, b1.w};
#pragma unroll
      for (int i = 0; i < 8; i++)
#pragma unroll
        for (int j = 0; j < 8; j++) acc[i][j] = fmaf(a[i], b[j], acc[i][j]);
    }
    __syncthreads();
  }

#pragma unroll
  for (int i = 0; i < 8; i++) {
    int r = m0 + ty * 8 + i;
    if (r >= M) continue;
#pragma unroll
    for (int j = 0; j < 8; j++) {
      int c = n0 + tx * 8 + j;
      if (c < N) p.store(z, r, c, acc[i][j]);
    }
  }
}

// ------------------------- GEMM problem definitions ------------------------

// Weff: per (tensor ti, head n, tap t): C(512c,512m) = wpT[ti][t] * W[ti] head n
struct WeffP {
  static constexpr bool BT = false;
  int M, N, K, lda, ldb;
  const float* wpT;
  const float* Wq;
  const float* Wk;
  const float* Wv;
  float* Weff;
  __device__ const float* Aptr(int z) const {
    int ti = z >> 5, t = z & 3;
    return wpT + ((size_t)(ti * 4 + t) << 18);
  }
  __device__ const float* Bptr(int z) const {
    int ti = z >> 5, n = (z & 31) >> 2;
    const float* W = (ti == 0) ? Wq : ((ti == 1) ? Wk : Wv);
    return W + (size_t)n * 512 * 512;
  }
  __device__ void store(int z, int r, int c, float v) const {
    int ti = z >> 5, n = (z & 31) >> 2, t = z & 3;
    Weff[(size_t)ti * 4096 * 2048 + (size_t)(n * 512 + r) * 2048 + t * 512 + c] = v;
  }
};

// Pooled projection: C(3136, Nout) = Xg * Weff^T -> scattered into (B,nh,LP,512)
struct PoolP {
  static constexpr bool BT = true;
  int M, N, K, lda, ldb;
  const float* Xg;
  const float* Weff;
  const float* bias;  // may be null
  float* out;
  int nh;
  __device__ const float* Aptr(int) const { return Xg; }
  __device__ const float* Bptr(int) const { return Weff; }
  __device__ void store(int, int r, int c, float v) const {
    int b = r / NB_, o = r % NB_;
    if (bias) v += bias[c];
    out[((size_t)(b * nh + (c >> 9)) * LP_ + 1 + o) * 512 + (c & 511)] = v;
  }
};

// Logits: per (b,n): C(1569,1569) = PQ * K2^T
struct LogitsP {
  static constexpr bool BT = true;
  int M, N, K, lda, ldb;
  const float* PQ;
  const float* K2;
  float* logits;
  __device__ const float* Aptr(int z) const { return PQ + (size_t)z * LP_ * 512; }
  __device__ const float* Bptr(int z) const { return K2 + (size_t)z * LP_ * 512; }
  __device__ void store(int z, int r, int c, float v) const {
    logits[(size_t)z * LP_ * LP_ + (size_t)r * LP_ + c] = v;
  }
};

// attn @ PV + residuals -> stacked (B, LP, 4096)
struct AVP {
  static constexpr bool BT = false;
  int M, N, K, lda, ldb;
  const float* attn;
  const float* PV;
  const float* PQ;
  float* stacked;
  __device__ const float* Aptr(int z) const { return attn + (size_t)z * LP_ * LP_; }
  __device__ const float* Bptr(int z) const { return PV + (size_t)z * LP_ * 512; }
  __device__ void store(int z, int r, int c, float v) const {
    float pq = PQ[(size_t)z * LP_ * 512 + (size_t)r * 512 + c];
    v += (r > 0 ? 2.f : 1.f) * pq;
    int b = z >> 3, n = z & 7;
    stacked[((size_t)b * LP_ + r) * 4096 + n * 512 + c] = v;
  }
};

// Final: y(3138,512) = stacked * Wd^T + bd + PX
struct FinalP {
  static constexpr bool BT = true;
  int M, N, K, lda, ldb;
  const float* stacked;
  const float* Wd;
  const float* bd;
  const float* PX;
  float* y;
  __device__ const float* Aptr(int) const { return stacked; }
  __device__ const float* Bptr(int) const { return Wd; }
  __device__ void store(int, int r, int c, float v) const {
    y[(size_t)r * 512 + c] = v + bd[c] + PX[(size_t)r * 512 + c];
  }
};

// ----------------------------- helper kernels ------------------------------

__global__ void k_transpose_wp(const float* wpq, const float* wpk, const float* wpv,
                               float* wpT) {
  size_t idx = (size_t)blockIdx.x * blockDim.x + threadIdx.x;
  if (idx >= SZ_WPT) return;
  int ti = (int)(idx / (512 * 512 * 4));
  int r = (int)(idx % (512 * 512 * 4));
  int c = r / 2048;
  int d = (r % 2048) >> 2;
  int t = r & 3;
  const float* wp = (ti == 0) ? wpq : ((ti == 1) ? wpk : wpv);
  wpT[((size_t)(ti * 4 + t) * 512 + c) * 512 + d] = wp[r];
}

__global__ void k_wxe(const float* wpx, float* WXe) {
  size_t idx = (size_t)blockIdx.x * blockDim.x + threadIdx.x;
  if (idx >= SZ_WXE) return;
  int c = (int)(idx / 2048);
  int t = (int)((idx % 2048) / 512);
  int m = (int)(idx & 511);
  WXe[idx] = wpx[(size_t)c * 2048 + m * 4 + t];
}

__global__ void k_bpool(const float* wpq, const float* wpk, const float* wpv,
                        const float* bq, const float* bk, const float* bv,
                        float* bpool) {
  int j = blockIdx.x * blockDim.x + threadIdx.x;
  if (j >= 3 * 4096) return;
  int ti = j / 4096, h = j % 4096, n = h >> 9, c = h & 511;
  const float* wp = (ti == 0) ? wpq : ((ti == 1) ? wpk : wpv);
  const float* b = (ti == 0) ? bq : ((ti == 1) ? bk : bv);
  float s = 0.f;
  for (int d = 0; d < 512; d++) {
    float bb = b[n * 512 + d];
    const float* w = wp + (size_t)c * 2048 + d * 4;
    s += (w[0] + w[1] + w[2] + w[3]) * bb;
  }
  bpool[j] = s;
}

__global__ void k_gather(const float* x, float* Xg) {
  size_t idx = (size_t)blockIdx.x * blockDim.x + threadIdx.x;
  if (idx >= SZ_XG) return;
  int r = (int)(idx / 2048);
  int col = (int)(idx & 2047);
  int t = col >> 9, m = col & 511;
  int b = r / NB_, o = r % NB_;
  int t2 = o / 196, hh = (o / 14) % 14, ww = o % 14;
  int kh = t >> 1, kw = t & 1;
  int row = 1 + (t2 * 28 + 2 * hh + kh) * 28 + 2 * ww + kw;
  Xg[idx] = x[((size_t)b * L_ + row) * 512 + m];
}

__global__ void k_cls(const float* x, const float* Wq, const float* bq,
                      const float* Wk, const float* bk, const float* Wv,
                      const float* bv, float* PQ, float* PK, float* PV,
                      float* PX) {
  int idx = blockIdx.x * blockDim.x + threadIdx.x;
  if (idx < 2 * 12288) {
    int b = idx / 12288, j = idx % 12288, ti = j / 4096, jj = j & 4095;
    const float* W = (ti == 0) ? Wq : ((ti == 1) ? Wk : Wv);
    const float* bias = (ti == 0) ? bq : ((ti == 1) ? bk : bv);
    const float* xr = x + (size_t)b * L_ * 512;
    const float* wr = W + (size_t)jj * 512;
    float s = bias[jj];
    for (int m = 0; m < 512; m++) s += xr[m] * wr[m];
    int n = jj >> 9, c = jj & 511;
    float* out = (ti == 0) ? PQ : ((ti == 1) ? PK : PV);
    out[(size_t)(b * 8 + n) * LP_ * 512 + c] = s;
  } else if (idx < 2 * 12288 + 2 * 512) {
    int k = idx - 2 * 12288;
    int b = k >> 9, c = k & 511;
    PX[(size_t)b * LP_ * 512 + c] = x[(size_t)b * L_ * 512 + c];
  }
}

__device__ __forceinline__ float sincos_val(int pos, int c, int dim) {
  int half = dim / 2;
  bool is_cos = c >= half;
  int i = is_cos ? c - half : c;
  float omega = powf(10000.f, -((float)i) / (float)half);
  float ang = (float)pos * omega;
  return is_cos ? cosf(ang) : sinf(ang);
}

__global__ void k_emb(float* emb) {
  size_t idx = (size_t)blockIdx.x * blockDim.x + threadIdx.x;
  if (idx >= SZ_EMB) return;
  int k = (int)(idx >> 9);
  int c = (int)(idx & 511);
  int t2 = k / 196, h2 = (k / 14) % 14, w2 = k % 14;
  float v;
  if (c < 170) v = sincos_val(t2, c, 170);
  else if (c < 340) v = sincos_val(h2, c - 170, 170);
  else v = sincos_val(w2, c - 340, 172);
  emb[idx] = v;
}

__global__ void k_k2(const float* PK, const float* emb, float* K2) {
  size_t idx = (size_t)blockIdx.x * blockDim.x + threadIdx.x;
  if (idx >= SZ_P) return;
  size_t rem = idx % ((size_t)LP_ * 512);
  int k = (int)(rem >> 9);
  int c = (int)(rem & 511);
  float v = SCALE_ * PK[idx];
  if (k > 0) v += emb[(size_t)(k - 1) * 512 + c];
  K2[idx] = v;
}

__global__ void k_row0(const float* PQ, const float* PK, float* logits) {
  int z = blockIdx.y;
  int kq = blockIdx.x * 8 + (threadIdx.x >> 5);
  int lane = threadIdx.x & 31;
  if (kq >= LP_) return;
  const float* q = PQ + (size_t)z * LP_ * 512;
  const float* kr = PK + (size_t)z * LP_ * 512 + (size_t)kq * 512;
  float s = 0.f;
  for (int i = lane; i < 512; i += 32) s += q[i] * kr[i];
#pragma unroll
  for (int o = 16; o; o >>= 1) s += __shfl_xor_sync(0xFFFFFFFFu, s, o);
  if (lane == 0) logits[(size_t)z * LP_ * LP_ + kq] = s * SCALE_;
}

__global__ void k_softmax(float* logits) {
  int z = blockIdx.y, q = blockIdx.x;
  float* row = logits + ((size_t)z * LP_ + q) * LP_;
  int tid = threadIdx.x;
  __shared__ float red[256];
  float mx = -1e30f;
  for (int i = tid; i < LP_; i += 256) mx = fmaxf(mx, row[i]);
  red[tid] = mx;
  __syncthreads();
  for (int s = 128; s > 0; s >>= 1) {
    if (tid < s) red[tid] = fmaxf(red[tid], red[tid + s]);
    __syncthreads();
  }
  mx = red[0];
  __syncthreads();
  float sum = 0.f;
  for (int i = tid; i < LP_; i += 256) {
    float e = expf(row[i] - mx);
    row[i] = e;
    sum += e;
  }
  red[tid] = sum;
  __syncthreads();
  for (int s = 128; s > 0; s >>= 1) {
    if (tid < s) red[tid] += red[tid + s];
    __syncthreads();
  }
  float inv = 1.f / red[0];
  for (int i = tid; i < LP_; i += 256) row[i] *= inv;
}

__global__ void k_ln(float* y, const float* gamma, const float* beta) {
  int row = blockIdx.x;
  float* yr = y + (size_t)row * 512;
  int tid = threadIdx.x;
  float v0 = yr[tid], v1 = yr[tid + 256];
  __shared__ float red[256];
  red[tid] = v0 + v1;
  __syncthreads();
  for (int s = 128; s > 0; s >>= 1) {
    if (tid < s) red[tid] += red[tid + s];
    __syncthreads();
  }
  float mu = red[0] * (1.f / 512.f);
  __syncthreads();
  float d0 = v0 - mu, d1 = v1 - mu;
  red[tid] = d0 * d0 + d1 * d1;
  __syncthreads();
  for (int s = 128; s > 0; s >>= 1) {
    if (tid < s) red[tid] += red[tid + s];
    __syncthreads();
  }
  float inv = rsqrtf(red[0] * (1.f / 512.f) + 1e-5f);
  yr[tid] = d0 * inv * gamma[tid] + beta[tid];
  yr[tid + 256] = d1 * inv * gamma[tid + 256] + beta[tid + 256];
}

// ------------------------------- launcher ----------------------------------

extern "C" void kernel_launch(void* const* d_in, const int* in_sizes, int n_in,
                              void* d_out, int out_size) {
  (void)in_sizes; (void)n_in; (void)out_size;
  const float* x   = (const float*)d_in[0];
  const float* Wq  = (const float*)d_in[1];
  const float* bq  = (const float*)d_in[2];
  const float* Wk  = (const float*)d_in[3];
  const float* bk  = (const float*)d_in[4];
  const float* Wv  = (const float*)d_in[5];
  const float* bv  = (const float*)d_in[6];
  const float* wpq = (const float*)d_in[7];
  const float* wpk = (const float*)d_in[8];
  const float* wpv = (const float*)d_in[9];
  const float* wpx = (const float*)d_in[10];
  const float* Wd  = (const float*)d_in[11];
  const float* bd  = (const float*)d_in[12];
  const float* gamma = (const float*)d_in[13];
  const float* beta  = (const float*)d_in[14];
  float* y = (float*)d_out;

  float* S = nullptr;
  cudaGetSymbolAddress((void**)&S, g_scratch);

  float* wpT   = S + OFF_WPT;
  float* Weff  = S + OFF_WEFF;
  float* WXe   = S + OFF_WXE;
  float* bpool = S + OFF_BP;
  float* Xg    = S + OFF_XG;
  float* PQ    = S + OFF_PQ;
  float* PK    = S + OFF_PK;
  float* PV    = S + OFF_PV;
  float* K2    = S + OFF_K2;
  float* PX    = S + OFF_PX;
  float* emb   = S + OFF_EMB;
  float* lg    = S + OFF_LG;
  float* st    = S + OFF_ST;

  k_transpose_wp<<<(int)((SZ_WPT + 255) / 256), 256>>>(wpq, wpk, wpv, wpT);
  k_wxe<<<(int)((SZ_WXE + 255) / 256), 256>>>(wpx, WXe);
  k_bpool<<<(3 * 4096 + 255) / 256, 256>>>(wpq, wpk, wpv, bq, bk, bv, bpool);

  {
    WeffP p;
    p.M = 512; p.N = 512; p.K = 512; p.lda = 512; p.ldb = 512;
    p.wpT = wpT; p.Wq = Wq; p.Wk = Wk; p.Wv = Wv; p.Weff = Weff;
    gemm_tile<WeffP><<<dim3(4, 4, 96), 256>>>(p);
  }

  k_gather<<<(int)((SZ_XG + 255) / 256), 256>>>(x, Xg);

  {
    PoolP p;
    p.M = B_ * NB_; p.K = 2048; p.lda = 2048; p.ldb = 2048;
    p.Xg = Xg;
    p.N = DH_; p.nh = 8;
    p.Weff = Weff;                    p.bias = bpool;          p.out = PQ;
    gemm_tile<PoolP><<<dim3(32, 25, 1), 256>>>(p);
    p.Weff = Weff + (size_t)4096 * 2048; p.bias = bpool + 4096; p.out = PK;
    gemm_tile<PoolP><<<dim3(32, 25, 1), 256>>>(p);
    p.Weff = Weff + (size_t)2 * 4096 * 2048; p.bias = bpool + 8192; p.out = PV;
    gemm_tile<PoolP><<<dim3(32, 25, 1), 256>>>(p);
    p.N = 512; p.nh = 1;
    p.Weff = WXe; p.bias = nullptr; p.out = PX;
    gemm_tile<PoolP><<<dim3(4, 25, 1), 256>>>(p);
  }

  k_cls<<<(2 * 12288 + 2 * 512 + 255) / 256, 256>>>(x, Wq, bq, Wk, bk, Wv, bv,
                                                    PQ, PK, PV, PX);
  k_emb<<<(int)((SZ_EMB + 255) / 256), 256>>>(emb);
  k_k2<<<(int)((SZ_P + 255) / 256), 256>>>(PK, emb, K2);

  {
    LogitsP p;
    p.M = LP_; p.N = LP_; p.K = 512; p.lda = 512; p.ldb = 512;
    p.PQ = PQ; p.K2 = K2; p.logits = lg;
    gemm_tile<LogitsP><<<dim3(13, 13, 16), 256>>>(p);
  }

  k_row0<<<dim3((LP_ + 7) / 8, 16), 256>>>(PQ, PK, lg);
  k_softmax<<<dim3(LP_, 16), 256>>>(lg);

  {
    AVP p;
    p.M = LP_; p.N = 512; p.K = LP_; p.lda = LP_; p.ldb = 512;
    p.attn = lg; p.PV = PV; p.PQ = PQ; p.stacked = st;
    gemm_tile<AVP><<<dim3(4, 13, 16), 256>>>(p);
  }

  {
    FinalP p;
    p.M = B_ * LP_; p.N = 512; p.K = 4096; p.lda = 4096; p.ldb = 4096;
    p.stacked = st; p.Wd = Wd; p.bd = bd; p.PX = PX; p.y = y;
    gemm_tile<FinalP><<<dim3(4, 25, 1), 256>>>(p);
  }

  k_ln<<<B_ * LP_, 256>>>(y, gamma, beta);
}